// round 9
// baseline (speedup 1.0000x reference)
#include <cuda_runtime.h>
#include <cuda_bf16.h>

#define TOKENS 2048
#define DDIM   1024
#define PDIM   32
#define NPAT   256
#define TOPK   4
#define NPAIRS (TOKENS * TOPK)            // 8192
#define CHUNK  32
#define MAXCHUNKS (NPAIRS / CHUNK + NPAT) // 512
#define ASPLIT 8
#define WPAD   36

// ---------------- global scratch (static, allocation-free) ----------------
__device__ int   g_eidx[NPAIRS];
__device__ float g_wt[NPAIRS];
__device__ int   g_list[NPAIRS];
__device__ int   g_tiles[MAXCHUNKS];
__device__ int   g_nchunks;
__device__ float g_hwT[DDIM * PDIM];
__device__ float g_keysT[PDIM * NPAT];
__device__ float g_papart[(size_t)NPAIRS * ASPLIT * PDIM];  // 8 MB
__device__ uint2 g_poutb[(size_t)NPAIRS * DDIM / 4];        // bf16 pout

__device__ __forceinline__ float my_silu(float z) {
    return z / (1.0f + __expf(-z));
}

// ---------------- kernel 0: transpose hasher_w and keys ----------------
__global__ void prep_kernel(const float* __restrict__ hw,
                            const float* __restrict__ keys)
{
    const int tid = blockIdx.x * 256 + threadIdx.x;
    if (tid < (PDIM * DDIM) / 4) {
        const int p = tid >> 8;
        const float4 v = ((const float4*)hw)[tid];
        const int d = (tid & 255) * 4;
        g_hwT[(d + 0) * PDIM + p] = v.x;
        g_hwT[(d + 1) * PDIM + p] = v.y;
        g_hwT[(d + 2) * PDIM + p] = v.z;
        g_hwT[(d + 3) * PDIM + p] = v.w;
    }
    if (tid < (NPAT * PDIM) / 4) {
        const int n = tid >> 3;
        const int q = tid & 7;
        const float4 v = ((const float4*)keys)[tid];
        g_keysT[(q * 4 + 0) * NPAT + n] = v.x;
        g_keysT[(q * 4 + 1) * NPAT + n] = v.y;
        g_keysT[(q * 4 + 2) * NPAT + n] = v.z;
        g_keysT[(q * 4 + 3) * NPAT + n] = v.w;
    }
}

// ---------------- kernel 1: routing — 8 tokens/block, 256 blocks ----------------
__global__ __launch_bounds__(256)
void routing_kernel(const float* __restrict__ x,
                    const float* __restrict__ scale)
{
    __shared__ float wS[256 * WPAD];   // 36 KB
    __shared__ float shh[8][PDIM];

    const int tid  = threadIdx.x;
    const int warp = tid >> 5;
    const int lane = tid & 31;
    const int tok  = blockIdx.x * 8 + warp;

    const int p4 = lane & 7;
    const int dq = lane >> 3;

    float4 acc = make_float4(0.f, 0.f, 0.f, 0.f);
    const float* xr0 = x + (size_t)tok * DDIM;

    for (int slice = 0; slice < 4; slice++) {
        __syncthreads();
        {
            const float4* src = (const float4*)(g_hwT + slice * 256 * PDIM);
            #pragma unroll
            for (int k = 0; k < 8; k++) {
                const int i = tid + k * 256;
                const int r = i >> 3, q = i & 7;
                *(float4*)&wS[r * WPAD + q * 4] = src[i];
            }
        }
        __syncthreads();

        const float* xr = xr0 + slice * 256;
        #pragma unroll 2
        for (int db = 0; db < 256; db += 16) {
            const float4 xv = *(const float4*)(xr + db + dq * 4);
            const int wb = (db + dq * 4) * WPAD + p4 * 4;
            #pragma unroll
            for (int j = 0; j < 4; j++) {
                const float4 w = *(const float4*)&wS[wb + j * WPAD];
                const float s = (j==0)?xv.x:(j==1)?xv.y:(j==2)?xv.z:xv.w;
                acc.x += s*w.x; acc.y += s*w.y; acc.z += s*w.z; acc.w += s*w.w;
            }
        }
    }

    #pragma unroll
    for (int o = 8; o <= 16; o <<= 1) {
        acc.x += __shfl_xor_sync(0xFFFFFFFFu, acc.x, o);
        acc.y += __shfl_xor_sync(0xFFFFFFFFu, acc.y, o);
        acc.z += __shfl_xor_sync(0xFFFFFFFFu, acc.z, o);
        acc.w += __shfl_xor_sync(0xFFFFFFFFu, acc.w, o);
    }
    if (dq == 0) *(float4*)&shh[warp][p4 * 4] = acc;
    __syncthreads();

    {
        const float4* src = (const float4*)g_keysT;
        #pragma unroll
        for (int k = 0; k < 8; k++)
            ((float4*)wS)[tid + k * 256] = src[tid + k * 256];
    }
    __syncthreads();

    float v[8];
    #pragma unroll
    for (int j = 0; j < 8; j++) v[j] = 0.f;
    #pragma unroll 4
    for (int p = 0; p < PDIM; p++) {
        const float hp = shh[warp][p];
        const int kb = p * NPAT + lane;
        #pragma unroll
        for (int j = 0; j < 8; j++)
            v[j] += hp * wS[kb + 32 * j];
    }

    float wv[TOPK]; int widx[TOPK];
    #pragma unroll
    for (int k = 0; k < TOPK; k++) {
        float bv = v[0]; int bj = 0;
        #pragma unroll
        for (int j = 1; j < 8; j++)
            if (v[j] > bv) { bv = v[j]; bj = j; }
        int bidx = lane + 32 * bj;
        #pragma unroll
        for (int o = 16; o; o >>= 1) {
            float ov = __shfl_xor_sync(0xFFFFFFFFu, bv, o);
            int   oi = __shfl_xor_sync(0xFFFFFFFFu, bidx, o);
            if (ov > bv || (ov == bv && oi < bidx)) { bv = ov; bidx = oi; }
        }
        wv[k] = bv; widx[k] = bidx;
        if ((bidx & 31) == lane) v[bidx >> 5] = -1e30f;
    }

    if (lane == 0) {
        float m = wv[0];
        #pragma unroll
        for (int k = 1; k < TOPK; k++) m = fmaxf(m, wv[k]);
        float e[TOPK], s = 0.0f;
        #pragma unroll
        for (int k = 0; k < TOPK; k++) { e[k] = __expf(wv[k] - m); s += e[k]; }
        const float inv = scale[0] / s;
        #pragma unroll
        for (int k = 0; k < TOPK; k++) {
            const int pair = (tok << 2) | k;
            g_eidx[pair] = widx[k];
            g_wt[pair]   = e[k] * inv;
        }
    }
}

// ---------------- kernel 2: scheduler ----------------
__global__ __launch_bounds__(NPAT, 1)
void build_tiles_kernel()
{
    __shared__ int cnt[NPAT];
    __shared__ int scn[NPAT];
    __shared__ int base[NPAT];
    __shared__ int off[NPAT];

    const int t = threadIdx.x;
    cnt[t] = 0; off[t] = 0;
    __syncthreads();

    for (int i = t; i < NPAIRS; i += NPAT)
        atomicAdd(&cnt[g_eidx[i]], 1);
    __syncthreads();

    scn[t] = cnt[t];
    __syncthreads();
    for (int o = 1; o < NPAT; o <<= 1) {
        int add = (t >= o) ? scn[t - o] : 0;
        __syncthreads();
        scn[t] += add;
        __syncthreads();
    }
    base[t] = scn[t] - cnt[t];
    __syncthreads();

    for (int i = t; i < NPAIRS; i += NPAT) {
        const int e = g_eidx[i];
        const int slot = atomicAdd(&off[e], 1);
        g_list[base[e] + slot] = i;
    }

    const int nch = (cnt[t] + CHUNK - 1) / CHUNK;
    scn[t] = nch;
    __syncthreads();
    for (int o = 1; o < NPAT; o <<= 1) {
        int add = (t >= o) ? scn[t - o] : 0;
        __syncthreads();
        scn[t] += add;
        __syncthreads();
    }
    const int cbase = scn[t] - nch;
    for (int i = 0; i < nch; i++) {
        const int start = base[t] + i * CHUNK;
        const int c     = min(CHUNK, cnt[t] - i * CHUNK);
        g_tiles[cbase + i] = (t << 19) | (start << 6) | c;
    }
    if (t == NPAT - 1) g_nchunks = scn[t];
}

// ---------------- kernel 3: phase A — 256 thr, 4 pairs/warp, int indexing ----------------
__global__ __launch_bounds__(256)
void phaseA_kernel(const float* __restrict__ x,
                   const float* __restrict__ vd)
{
    __shared__ float wS[128 * WPAD];     // 18 KB
    __shared__ float xS[CHUNK * 128];    // 16 KB
    __shared__ int   spair[CHUNK];

    const int chunkId = blockIdx.x >> 3;
    const int dsplit  = blockIdx.x & 7;
    if (chunkId >= g_nchunks) return;

    const int te    = g_tiles[chunkId];
    const int e     = te >> 19;
    const int start = (te >> 6) & 0x1FFF;
    const int cnt   = te & 0x3F;

    const int tid = threadIdx.x;
    if (tid < CHUNK) spair[tid] = g_list[start + min(tid, cnt - 1)];
    __syncthreads();

    // stage Vd slice (1024 float4)
    {
        const float4* src = (const float4*)(vd + ((size_t)e * DDIM + dsplit * 128) * PDIM);
        #pragma unroll
        for (int k = 0; k < 4; k++) {
            const int i = tid + k * 256;
            const int r = i >> 3, q = i & 7;
            *(float4*)&wS[r * WPAD + q * 4] = src[i];
        }
    }
    // stage x slices
    {
        const int nld = cnt << 5;
        for (int i = tid; i < nld; i += 256) {
            const int r = i >> 5, c = i & 31;
            ((float4*)xS)[(r << 5) + c] =
                ((const float4*)(x + (size_t)(spair[r] >> 2) * DDIM + dsplit * 128))[c];
        }
    }
    __syncthreads();

    const int warp = tid >> 5;
    const int lane = tid & 31;
    const int g0   = warp * 4;
    if (g0 >= cnt) return;

    const int p4 = lane & 7;
    const int dq = lane >> 3;

    int xo[4];
    #pragma unroll
    for (int t = 0; t < 4; t++)
        xo[t] = (min(g0 + t, cnt - 1) << 7) + dq * 4;

    float4 a0 = make_float4(0.f,0.f,0.f,0.f), a1 = a0, a2 = a0, a3 = a0;

    #pragma unroll 2
    for (int db = 0; db < 128; db += 16) {
        const float4 xv0 = *(const float4*)&xS[xo[0] + db];
        const float4 xv1 = *(const float4*)&xS[xo[1] + db];
        const float4 xv2 = *(const float4*)&xS[xo[2] + db];
        const float4 xv3 = *(const float4*)&xS[xo[3] + db];
        const int wb = (db + dq * 4) * WPAD + p4 * 4;
        #pragma unroll
        for (int j = 0; j < 4; j++) {
            const float4 w = *(const float4*)&wS[wb + j * WPAD];
            const float s0 = (j==0)?xv0.x:(j==1)?xv0.y:(j==2)?xv0.z:xv0.w;
            const float s1 = (j==0)?xv1.x:(j==1)?xv1.y:(j==2)?xv1.z:xv1.w;
            const float s2 = (j==0)?xv2.x:(j==1)?xv2.y:(j==2)?xv2.z:xv2.w;
            const float s3 = (j==0)?xv3.x:(j==1)?xv3.y:(j==2)?xv3.z:xv3.w;
            a0.x += s0*w.x; a0.y += s0*w.y; a0.z += s0*w.z; a0.w += s0*w.w;
            a1.x += s1*w.x; a1.y += s1*w.y; a1.z += s1*w.z; a1.w += s1*w.w;
            a2.x += s2*w.x; a2.y += s2*w.y; a2.z += s2*w.z; a2.w += s2*w.w;
            a3.x += s3*w.x; a3.y += s3*w.y; a3.z += s3*w.z; a3.w += s3*w.w;
        }
    }

    float4* accs[4] = { &a0, &a1, &a2, &a3 };
    #pragma unroll
    for (int t = 0; t < 4; t++) {
        float4& a = *accs[t];
        #pragma unroll
        for (int o = 8; o <= 16; o <<= 1) {
            a.x += __shfl_xor_sync(0xFFFFFFFFu, a.x, o);
            a.y += __shfl_xor_sync(0xFFFFFFFFu, a.y, o);
            a.z += __shfl_xor_sync(0xFFFFFFFFu, a.z, o);
            a.w += __shfl_xor_sync(0xFFFFFFFFu, a.w, o);
        }
    }
    if (dq == 0) {
        #pragma unroll
        for (int t = 0; t < 4; t++) {
            if (g0 + t < cnt) {
                float* dst = g_papart
                    + ((size_t)spair[g0 + t] * ASPLIT + dsplit) * PDIM + p4 * 4;
                *(float4*)dst = *accs[t];
            }
        }
    }
}

// ---------------- kernel 4: phase B — fused silu, 256 thr, bf16 out ----------------
__global__ __launch_bounds__(256)
void phaseB_kernel(const float* __restrict__ vu)
{
    __shared__ float vuS[PDIM * 128];    // 16 KB
    __shared__ float projS[CHUNK * PDIM];// 4 KB
    __shared__ int   spair[CHUNK];

    const int chunkId = blockIdx.x >> 3;
    const int dsplit  = blockIdx.x & 7;
    if (chunkId >= g_nchunks) return;

    const int te    = g_tiles[chunkId];
    const int e     = te >> 19;
    const int start = (te >> 6) & 0x1FFF;
    const int cnt   = te & 0x3F;

    const int tid = threadIdx.x;
    if (tid < CHUNK) spair[tid] = g_list[start + min(tid, cnt - 1)];
    __syncthreads();

    // stage Vu slice (1024 float4)
    {
        const float4* src = (const float4*)(vu + (size_t)e * PDIM * DDIM + dsplit * 128);
        #pragma unroll
        for (int k = 0; k < 4; k++) {
            const int i = tid + k * 256;
            const int r = i >> 5, c = i & 31;
            ((float4*)vuS)[(r << 5) + c] = src[r * (DDIM / 4) + c];
        }
    }
    // fused: reconstruct proj from 8 partials (fixed order), silu, weight
    {
        const int pr = tid >> 3;
        const int q  = tid & 7;
        const int pair = spair[pr];
        const float wt = g_wt[pair];
        const float* pp = g_papart + ((size_t)pair * ASPLIT) * PDIM + q * 4;
        float4 s = make_float4(0.f, 0.f, 0.f, 0.f);
        #pragma unroll
        for (int j = 0; j < ASPLIT; j++) {
            const float4 v = *(const float4*)(pp + j * PDIM);
            s.x += v.x; s.y += v.y; s.z += v.z; s.w += v.w;
        }
        float4 o;
        o.x = wt * my_silu(s.x);
        o.y = wt * my_silu(s.y);
        o.z = wt * my_silu(s.z);
        o.w = wt * my_silu(s.w);
        *(float4*)&projS[pr * PDIM + q * 4] = o;
    }
    __syncthreads();

    const int warp = tid >> 5;
    const int lane = tid & 31;
    const int g0   = warp * 4;
    if (g0 >= cnt) return;

    int po[4];
    #pragma unroll
    for (int t = 0; t < 4; t++)
        po[t] = min(g0 + t, CHUNK - 1) * PDIM;

    float4 o0 = make_float4(0.f,0.f,0.f,0.f), o1 = o0, o2 = o0, o3 = o0;
    const int l4 = lane * 4;

    #pragma unroll
    for (int pq = 0; pq < 8; pq++) {
        const float4 pj0 = *(const float4*)&projS[po[0] + pq * 4];
        const float4 pj1 = *(const float4*)&projS[po[1] + pq * 4];
        const float4 pj2 = *(const float4*)&projS[po[2] + pq * 4];
        const float4 pj3 = *(const float4*)&projS[po[3] + pq * 4];
        #pragma unroll
        for (int j = 0; j < 4; j++) {
            const float4 w = *(const float4*)&vuS[(pq * 4 + j) * 128 + l4];
            const float s0 = (j==0)?pj0.x:(j==1)?pj0.y:(j==2)?pj0.z:pj0.w;
            const float s1 = (j==0)?pj1.x:(j==1)?pj1.y:(j==2)?pj1.z:pj1.w;
            const float s2 = (j==0)?pj2.x:(j==1)?pj2.y:(j==2)?pj2.z:pj2.w;
            const float s3 = (j==0)?pj3.x:(j==1)?pj3.y:(j==2)?pj3.z:pj3.w;
            o0.x += s0*w.x; o0.y += s0*w.y; o0.z += s0*w.z; o0.w += s0*w.w;
            o1.x += s1*w.x; o1.y += s1*w.y; o1.z += s1*w.z; o1.w += s1*w.w;
            o2.x += s2*w.x; o2.y += s2*w.y; o2.z += s2*w.z; o2.w += s2*w.w;
            o3.x += s3*w.x; o3.y += s3*w.y; o3.z += s3*w.z; o3.w += s3*w.w;
        }
    }

    const int dmem = dsplit * 128 + l4;
    float4 oo[4] = { o0, o1, o2, o3 };
    #pragma unroll
    for (int t = 0; t < 4; t++) {
        if (g0 + t < cnt) {
            __nv_bfloat162 lo = __floats2bfloat162_rn(oo[t].x, oo[t].y);
            __nv_bfloat162 hi = __floats2bfloat162_rn(oo[t].z, oo[t].w);
            uint2 u;
            u.x = *(unsigned int*)&lo;
            u.y = *(unsigned int*)&hi;
            g_poutb[((size_t)spair[g0 + t] * DDIM + dmem) >> 2] = u;
        }
    }
}

// ---------------- kernel 5: combine ----------------
__global__ __launch_bounds__(256)
void combine_kernel(const float* __restrict__ x, float* __restrict__ out)
{
    const int tok = blockIdx.x;
    const int t   = threadIdx.x;
    float4 o = ((const float4*)(x + (size_t)tok * DDIM))[t];
    #pragma unroll
    for (int k = 0; k < TOPK; k++) {
        const uint2 u = g_poutb[((size_t)((tok << 2) | k) * DDIM) / 4 + t];
        const __nv_bfloat162 lo = *(const __nv_bfloat162*)&u.x;
        const __nv_bfloat162 hi = *(const __nv_bfloat162*)&u.y;
        const float2 flo = __bfloat1622float2(lo);
        const float2 fhi = __bfloat1622float2(hi);
        o.x += flo.x; o.y += flo.y; o.z += fhi.x; o.w += fhi.y;
    }
    ((float4*)(out + (size_t)tok * DDIM))[t] = o;
}

// ---------------- launch ----------------
extern "C" void kernel_launch(void* const* d_in, const int* in_sizes, int n_in,
                              void* d_out, int out_size) {
    const float* x     = (const float*)d_in[0];
    const float* hw    = (const float*)d_in[1];
    const float* keys  = (const float*)d_in[2];
    const float* vd    = (const float*)d_in[3];
    const float* vu    = (const float*)d_in[4];
    const float* scale = (const float*)d_in[5];
    float* out = (float*)d_out;

    prep_kernel<<<32, 256>>>(hw, keys);
    routing_kernel<<<TOKENS / 8, 256>>>(x, scale);
    build_tiles_kernel<<<1, NPAT>>>();
    phaseA_kernel<<<MAXCHUNKS * ASPLIT, 256>>>(x, vd);
    phaseB_kernel<<<MAXCHUNKS * 8, 256>>>(vu);
    combine_kernel<<<TOKENS, 256>>>(x, out);
}

// round 10
// speedup vs baseline: 1.1339x; 1.1339x over previous
#include <cuda_runtime.h>
#include <cuda_bf16.h>

#define TOKENS 2048
#define DDIM   1024
#define PDIM   32
#define NPAT   256
#define TOPK   4
#define NPAIRS (TOKENS * TOPK)            // 8192
#define CHUNK  32
#define MAXCHUNKS (NPAIRS / CHUNK + NPAT) // 512
#define ASPLIT 4
#define WPAD   36     // Vd/proj row stride (floats)
#define XSTRIDE 260   // x row stride
#define RSTRIDE 33    // reduce-buffer row stride
#define VSTRIDE 264   // Vu row stride

// ---------------- global scratch (static, allocation-free) ----------------
__device__ int   g_eidx[NPAIRS];
__device__ float g_wt[NPAIRS];
__device__ int   g_list[NPAIRS];
__device__ int   g_tiles[MAXCHUNKS];
__device__ int   g_nchunks;
__device__ float g_hwT[DDIM * PDIM];
__device__ float g_keysT[PDIM * NPAT];
__device__ float g_papart[NPAIRS * ASPLIT * PDIM];        // 4 MB
__device__ unsigned int g_poutb[NPAIRS * DDIM / 2];       // bf16x2, 16.8 MB

__device__ __forceinline__ float my_silu(float z) {
    return z / (1.0f + __expf(-z));
}

__device__ __forceinline__ void mma_tf32(float& c0, float& c1, float& c2, float& c3,
                                         unsigned int a0, unsigned int a1,
                                         unsigned int a2, unsigned int a3,
                                         unsigned int b0, unsigned int b1) {
    asm volatile(
        "mma.sync.aligned.m16n8k8.row.col.f32.tf32.tf32.f32 "
        "{%0,%1,%2,%3}, {%4,%5,%6,%7}, {%8,%9}, {%0,%1,%2,%3};"
        : "+f"(c0), "+f"(c1), "+f"(c2), "+f"(c3)
        : "r"(a0), "r"(a1), "r"(a2), "r"(a3), "r"(b0), "r"(b1));
}

// ---------------- kernel 0: transpose hasher_w and keys ----------------
__global__ void prep_kernel(const float* __restrict__ hw,
                            const float* __restrict__ keys)
{
    const int tid = blockIdx.x * 256 + threadIdx.x;
    if (tid < (PDIM * DDIM) / 4) {
        const int p = tid >> 8;
        const float4 v = ((const float4*)hw)[tid];
        const int d = (tid & 255) * 4;
        g_hwT[(d + 0) * PDIM + p] = v.x;
        g_hwT[(d + 1) * PDIM + p] = v.y;
        g_hwT[(d + 2) * PDIM + p] = v.z;
        g_hwT[(d + 3) * PDIM + p] = v.w;
    }
    if (tid < (NPAT * PDIM) / 4) {
        const int n = tid >> 3;
        const int q = tid & 7;
        const float4 v = ((const float4*)keys)[tid];
        g_keysT[(q * 4 + 0) * NPAT + n] = v.x;
        g_keysT[(q * 4 + 1) * NPAT + n] = v.y;
        g_keysT[(q * 4 + 2) * NPAT + n] = v.z;
        g_keysT[(q * 4 + 3) * NPAT + n] = v.w;
    }
}

// ---------------- kernel 1: routing — 8 tokens/block, 256 blocks ----------------
__global__ __launch_bounds__(256)
void routing_kernel(const float* __restrict__ x,
                    const float* __restrict__ scale)
{
    __shared__ float wS[256 * WPAD];
    __shared__ float shh[8][PDIM];

    const int tid  = threadIdx.x;
    const int warp = tid >> 5;
    const int lane = tid & 31;
    const int tok  = blockIdx.x * 8 + warp;

    const int p4 = lane & 7;
    const int dq = lane >> 3;

    float4 acc = make_float4(0.f, 0.f, 0.f, 0.f);
    const float* xr0 = x + (size_t)tok * DDIM;

    for (int slice = 0; slice < 4; slice++) {
        __syncthreads();
        {
            const float4* src = (const float4*)(g_hwT + slice * 256 * PDIM);
            #pragma unroll
            for (int k = 0; k < 8; k++) {
                const int i = tid + k * 256;
                const int r = i >> 3, q = i & 7;
                *(float4*)&wS[r * WPAD + q * 4] = src[i];
            }
        }
        __syncthreads();

        const float* xr = xr0 + slice * 256;
        #pragma unroll 2
        for (int db = 0; db < 256; db += 16) {
            const float4 xv = *(const float4*)(xr + db + dq * 4);
            const int wb = (db + dq * 4) * WPAD + p4 * 4;
            #pragma unroll
            for (int j = 0; j < 4; j++) {
                const float4 w = *(const float4*)&wS[wb + j * WPAD];
                const float s = (j==0)?xv.x:(j==1)?xv.y:(j==2)?xv.z:xv.w;
                acc.x += s*w.x; acc.y += s*w.y; acc.z += s*w.z; acc.w += s*w.w;
            }
        }
    }

    #pragma unroll
    for (int o = 8; o <= 16; o <<= 1) {
        acc.x += __shfl_xor_sync(0xFFFFFFFFu, acc.x, o);
        acc.y += __shfl_xor_sync(0xFFFFFFFFu, acc.y, o);
        acc.z += __shfl_xor_sync(0xFFFFFFFFu, acc.z, o);
        acc.w += __shfl_xor_sync(0xFFFFFFFFu, acc.w, o);
    }
    if (dq == 0) *(float4*)&shh[warp][p4 * 4] = acc;
    __syncthreads();

    {
        const float4* src = (const float4*)g_keysT;
        #pragma unroll
        for (int k = 0; k < 8; k++)
            ((float4*)wS)[tid + k * 256] = src[tid + k * 256];
    }
    __syncthreads();

    float v[8];
    #pragma unroll
    for (int j = 0; j < 8; j++) v[j] = 0.f;
    #pragma unroll 4
    for (int p = 0; p < PDIM; p++) {
        const float hp = shh[warp][p];
        const int kb = p * NPAT + lane;
        #pragma unroll
        for (int j = 0; j < 8; j++)
            v[j] += hp * wS[kb + 32 * j];
    }

    float wv[TOPK]; int widx[TOPK];
    #pragma unroll
    for (int k = 0; k < TOPK; k++) {
        float bv = v[0]; int bj = 0;
        #pragma unroll
        for (int j = 1; j < 8; j++)
            if (v[j] > bv) { bv = v[j]; bj = j; }
        int bidx = lane + 32 * bj;
        #pragma unroll
        for (int o = 16; o; o >>= 1) {
            float ov = __shfl_xor_sync(0xFFFFFFFFu, bv, o);
            int   oi = __shfl_xor_sync(0xFFFFFFFFu, bidx, o);
            if (ov > bv || (ov == bv && oi < bidx)) { bv = ov; bidx = oi; }
        }
        wv[k] = bv; widx[k] = bidx;
        if ((bidx & 31) == lane) v[bidx >> 5] = -1e30f;
    }

    if (lane == 0) {
        float m = wv[0];
        #pragma unroll
        for (int k = 1; k < TOPK; k++) m = fmaxf(m, wv[k]);
        float e[TOPK], s = 0.0f;
        #pragma unroll
        for (int k = 0; k < TOPK; k++) { e[k] = __expf(wv[k] - m); s += e[k]; }
        const float inv = scale[0] / s;
        #pragma unroll
        for (int k = 0; k < TOPK; k++) {
            const int pair = (tok << 2) | k;
            g_eidx[pair] = widx[k];
            g_wt[pair]   = e[k] * inv;
        }
    }
}

// ---------------- kernel 2: scheduler ----------------
__global__ __launch_bounds__(NPAT, 1)
void build_tiles_kernel()
{
    __shared__ int cnt[NPAT];
    __shared__ int scn[NPAT];
    __shared__ int base[NPAT];
    __shared__ int off[NPAT];

    const int t = threadIdx.x;
    cnt[t] = 0; off[t] = 0;
    __syncthreads();

    for (int i = t; i < NPAIRS; i += NPAT)
        atomicAdd(&cnt[g_eidx[i]], 1);
    __syncthreads();

    scn[t] = cnt[t];
    __syncthreads();
    for (int o = 1; o < NPAT; o <<= 1) {
        int add = (t >= o) ? scn[t - o] : 0;
        __syncthreads();
        scn[t] += add;
        __syncthreads();
    }
    base[t] = scn[t] - cnt[t];
    __syncthreads();

    for (int i = t; i < NPAIRS; i += NPAT) {
        const int e = g_eidx[i];
        const int slot = atomicAdd(&off[e], 1);
        g_list[base[e] + slot] = i;
    }

    const int nch = (cnt[t] + CHUNK - 1) / CHUNK;
    scn[t] = nch;
    __syncthreads();
    for (int o = 1; o < NPAT; o <<= 1) {
        int add = (t >= o) ? scn[t - o] : 0;
        __syncthreads();
        scn[t] += add;
        __syncthreads();
    }
    const int cbase = scn[t] - nch;
    for (int i = 0; i < nch; i++) {
        const int start = base[t] + i * CHUNK;
        const int c     = min(CHUNK, cnt[t] - i * CHUNK);
        g_tiles[cbase + i] = (t << 19) | (start << 6) | c;
    }
    if (t == NPAT - 1) g_nchunks = scn[t];
}

// ---------------- kernel 3: phase A — TF32 mma, 256-d slices ----------------
// dyn smem: wS[256][36] (9216 f) | xS[32][260] / redS[8][32][33] (8448 f)
__global__ __launch_bounds__(256)
void phaseA_kernel(const float* __restrict__ x,
                   const float* __restrict__ vd)
{
    extern __shared__ float sm[];
    float* wS = sm;
    float* xS = sm + 256 * WPAD;
    __shared__ int spair[CHUNK];

    const int chunkId = blockIdx.x >> 2;
    const int dsplit  = blockIdx.x & 3;
    if (chunkId >= g_nchunks) return;

    const int te    = g_tiles[chunkId];
    const int e     = te >> 19;
    const int start = (te >> 6) & 0x1FFF;
    const int cnt   = te & 0x3F;

    const int tid = threadIdx.x;
    if (tid < CHUNK) spair[tid] = g_list[start + min(tid, cnt - 1)];
    __syncthreads();

    // stage Vd slice [256 d][32 p], rows padded to 36
    {
        const float4* src = (const float4*)(vd + ((size_t)e * DDIM + dsplit * 256) * PDIM);
        #pragma unroll
        for (int k = 0; k < 8; k++) {
            const int i = tid + k * 256;      // 0..2047
            const int r = i >> 3, q = i & 7;
            *(float4*)&wS[r * WPAD + q * 4] = src[i];
        }
    }
    // stage x [32 tok][256 d], rows padded to 260
    {
        #pragma unroll
        for (int k = 0; k < 8; k++) {
            const int i = tid + k * 256;
            const int r = i >> 6, c = i & 63;
            *(float4*)&xS[r * XSTRIDE + c * 4] =
                ((const float4*)(x + (size_t)(spair[r] >> 2) * DDIM + dsplit * 256))[c];
        }
    }
    __syncthreads();

    const int warp = tid >> 5;
    const int lane = tid & 31;
    const int grp  = lane >> 2;
    const int t4   = lane & 3;
    const int kw   = warp * 32;   // this warp's 32-d sub-slice

    float c[2][4][4];
    #pragma unroll
    for (int mt = 0; mt < 2; mt++)
        #pragma unroll
        for (int nt = 0; nt < 4; nt++)
            #pragma unroll
            for (int j = 0; j < 4; j++) c[mt][nt][j] = 0.f;

    #pragma unroll
    for (int kk = 0; kk < 4; kk++) {
        const int kb = kw + kk * 8;
        unsigned int a[2][4];
        #pragma unroll
        for (int mt = 0; mt < 2; mt++) {
            const int r0 = (mt * 16 + grp) * XSTRIDE + kb + t4;
            const int r1 = (mt * 16 + grp + 8) * XSTRIDE + kb + t4;
            a[mt][0] = __float_as_uint(xS[r0]);
            a[mt][1] = __float_as_uint(xS[r1]);
            a[mt][2] = __float_as_uint(xS[r0 + 4]);
            a[mt][3] = __float_as_uint(xS[r1 + 4]);
        }
        #pragma unroll
        for (int nt = 0; nt < 4; nt++) {
            const unsigned int b0 = __float_as_uint(wS[(kb + t4) * WPAD + nt * 8 + grp]);
            const unsigned int b1 = __float_as_uint(wS[(kb + t4 + 4) * WPAD + nt * 8 + grp]);
            #pragma unroll
            for (int mt = 0; mt < 2; mt++)
                mma_tf32(c[mt][nt][0], c[mt][nt][1], c[mt][nt][2], c[mt][nt][3],
                         a[mt][0], a[mt][1], a[mt][2], a[mt][3], b0, b1);
        }
    }
    __syncthreads();   // everyone done reading xS

    // scatter C partials: redS[warp][tok][33] (reuse xS region)
    float* redS = xS;
    #pragma unroll
    for (int mt = 0; mt < 2; mt++) {
        #pragma unroll
        for (int nt = 0; nt < 4; nt++) {
            const int r0 = mt * 16 + grp;
            const int cc = nt * 8 + t4 * 2;
            redS[warp * 1056 + r0 * RSTRIDE + cc]           = c[mt][nt][0];
            redS[warp * 1056 + r0 * RSTRIDE + cc + 1]       = c[mt][nt][1];
            redS[warp * 1056 + (r0 + 8) * RSTRIDE + cc]     = c[mt][nt][2];
            redS[warp * 1056 + (r0 + 8) * RSTRIDE + cc + 1] = c[mt][nt][3];
        }
    }
    __syncthreads();

    // reduce 8 partials, write g_papart
    #pragma unroll
    for (int k = 0; k < 4; k++) {
        const int idx = tid + k * 256;     // 0..1023
        const int tok = idx >> 5, p = idx & 31;
        float s = 0.f;
        #pragma unroll
        for (int w = 0; w < 8; w++)
            s += redS[w * 1056 + tok * RSTRIDE + p];
        if (tok < cnt)
            g_papart[(spair[tok] * ASPLIT + dsplit) * PDIM + p] = s;
    }
}

// ---------------- kernel 4: phase B — TF32 mma, fused silu, bf16 out ----------------
__global__ __launch_bounds__(256)
void phaseB_kernel(const float* __restrict__ vu)
{
    __shared__ float vuS[PDIM * VSTRIDE];    // 33 KB
    __shared__ float projS[CHUNK * WPAD];    // 4.5 KB
    __shared__ int   spair[CHUNK];

    const int chunkId = blockIdx.x >> 2;
    const int dsplit  = blockIdx.x & 3;
    if (chunkId >= g_nchunks) return;

    const int te    = g_tiles[chunkId];
    const int e     = te >> 19;
    const int start = (te >> 6) & 0x1FFF;
    const int cnt   = te & 0x3F;

    const int tid = threadIdx.x;
    if (tid < CHUNK) spair[tid] = g_list[start + min(tid, cnt - 1)];
    __syncthreads();

    // stage Vu slice [32 p][256 d], rows padded to 264
    {
        const float4* src = (const float4*)(vu + (size_t)e * PDIM * DDIM + dsplit * 256);
        #pragma unroll
        for (int k = 0; k < 8; k++) {
            const int i = tid + k * 256;
            const int p = i >> 6, cc = i & 63;
            *(float4*)&vuS[p * VSTRIDE + cc * 4] = src[p * (DDIM / 4) + cc];
        }
    }
    // fused: reconstruct proj (sum 4 partials fixed order), silu, weight
    {
        const int pr = tid >> 3;
        const int q  = tid & 7;
        const int pair = spair[pr];
        const float wt = g_wt[pair];
        const float* pp = g_papart + pair * ASPLIT * PDIM + q * 4;
        float4 s = make_float4(0.f, 0.f, 0.f, 0.f);
        #pragma unroll
        for (int j = 0; j < ASPLIT; j++) {
            const float4 v = *(const float4*)(pp + j * PDIM);
            s.x += v.x; s.y += v.y; s.z += v.z; s.w += v.w;
        }
        float4 o;
        o.x = wt * my_silu(s.x);
        o.y = wt * my_silu(s.y);
        o.z = wt * my_silu(s.z);
        o.w = wt * my_silu(s.w);
        *(float4*)&projS[pr * WPAD + q * 4] = o;
    }
    __syncthreads();

    const int warp = tid >> 5;
    const int lane = tid & 31;
    const int grp  = lane >> 2;
    const int t4   = lane & 3;
    const int nw   = warp * 32;    // this warp's 32-d output range

    float c[2][4][4];
    #pragma unroll
    for (int mt = 0; mt < 2; mt++)
        #pragma unroll
        for (int nt = 0; nt < 4; nt++)
            #pragma unroll
            for (int j = 0; j < 4; j++) c[mt][nt][j] = 0.f;

    #pragma unroll
    for (int kk = 0; kk < 4; kk++) {
        const int kb = kk * 8;
        unsigned int a[2][4];
        #pragma unroll
        for (int mt = 0; mt < 2; mt++) {
            const int r0 = (mt * 16 + grp) * WPAD + kb + t4;
            const int r1 = (mt * 16 + grp + 8) * WPAD + kb + t4;
            a[mt][0] = __float_as_uint(projS[r0]);
            a[mt][1] = __float_as_uint(projS[r1]);
            a[mt][2] = __float_as_uint(projS[r0 + 4]);
            a[mt][3] = __float_as_uint(projS[r1 + 4]);
        }
        #pragma unroll
        for (int nt = 0; nt < 4; nt++) {
            const unsigned int b0 = __float_as_uint(vuS[(kb + t4) * VSTRIDE + nw + nt * 8 + grp]);
            const unsigned int b1 = __float_as_uint(vuS[(kb + t4 + 4) * VSTRIDE + nw + nt * 8 + grp]);
            #pragma unroll
            for (int mt = 0; mt < 2; mt++)
                mma_tf32(c[mt][nt][0], c[mt][nt][1], c[mt][nt][2], c[mt][nt][3],
                         a[mt][0], a[mt][1], a[mt][2], a[mt][3], b0, b1);
        }
    }

    // write bf16 pout
    #pragma unroll
    for (int mt = 0; mt < 2; mt++) {
        const int tok0 = mt * 16 + grp;
        const int tok1 = tok0 + 8;
        #pragma unroll
        for (int nt = 0; nt < 4; nt++) {
            const int col = dsplit * 256 + nw + nt * 8 + t4 * 2;
            if (tok0 < cnt) {
                __nv_bfloat162 v = __floats2bfloat162_rn(c[mt][nt][0], c[mt][nt][1]);
                g_poutb[(spair[tok0] * DDIM + col) >> 1] = *(unsigned int*)&v;
            }
            if (tok1 < cnt) {
                __nv_bfloat162 v = __floats2bfloat162_rn(c[mt][nt][2], c[mt][nt][3]);
                g_poutb[(spair[tok1] * DDIM + col) >> 1] = *(unsigned int*)&v;
            }
        }
    }
}

// ---------------- kernel 5: combine ----------------
__global__ __launch_bounds__(256)
void combine_kernel(const float* __restrict__ x, float* __restrict__ out)
{
    const int tok = blockIdx.x;
    const int t   = threadIdx.x;
    float4 o = ((const float4*)(x + (size_t)tok * DDIM))[t];
    #pragma unroll
    for (int k = 0; k < TOPK; k++) {
        const uint2 u = *(const uint2*)&g_poutb[((tok << 2) | k) * (DDIM / 2) + t * 2];
        const __nv_bfloat162 lo = *(const __nv_bfloat162*)&u.x;
        const __nv_bfloat162 hi = *(const __nv_bfloat162*)&u.y;
        const float2 flo = __bfloat1622float2(lo);
        const float2 fhi = __bfloat1622float2(hi);
        o.x += flo.x; o.y += flo.y; o.z += fhi.x; o.w += fhi.y;
    }
    ((float4*)(out + (size_t)tok * DDIM))[t] = o;
}

// ---------------- launch ----------------
extern "C" void kernel_launch(void* const* d_in, const int* in_sizes, int n_in,
                              void* d_out, int out_size) {
    const float* x     = (const float*)d_in[0];
    const float* hw    = (const float*)d_in[1];
    const float* keys  = (const float*)d_in[2];
    const float* vd    = (const float*)d_in[3];
    const float* vu    = (const float*)d_in[4];
    const float* scale = (const float*)d_in[5];
    float* out = (float*)d_out;

    const int smemA = (256 * WPAD + 8 * 32 * RSTRIDE) * (int)sizeof(float);  // 70656 B
    cudaFuncSetAttribute(phaseA_kernel,
                         cudaFuncAttributeMaxDynamicSharedMemorySize, smemA);

    prep_kernel<<<32, 256>>>(hw, keys);
    routing_kernel<<<TOKENS / 8, 256>>>(x, scale);
    build_tiles_kernel<<<1, NPAT>>>();
    phaseA_kernel<<<MAXCHUNKS * 4, 256, smemA>>>(x, vd);
    phaseB_kernel<<<MAXCHUNKS * 4, 256>>>(vu);
    combine_kernel<<<TOKENS, 256>>>(x, out);
}

// round 11
// speedup vs baseline: 1.1773x; 1.0383x over previous
#include <cuda_runtime.h>
#include <cuda_bf16.h>

#define TOKENS 2048
#define DDIM   1024
#define PDIM   32
#define NPAT   256
#define TOPK   4
#define NPAIRS (TOKENS * TOPK)            // 8192
#define CHUNK  32
#define MAXCHUNKS (NPAIRS / CHUNK + NPAT) // 512
#define WPAD   36     // Vd/proj row stride (floats)
#define SSTRIDE 132   // x / Vu slice row stride (floats)
#define BUFSZ  8832   // per-stage buffer: Vd[128][36]=4608 + x[32][132]=4224

// ---------------- global scratch (static, allocation-free) ----------------
__device__ int   g_eidx[NPAIRS];
__device__ float g_wt[NPAIRS];
__device__ int   g_list[NPAIRS];
__device__ int   g_tiles[MAXCHUNKS];
__device__ int   g_nchunks;
__device__ float g_hwT[DDIM * PDIM];
__device__ float g_keysT[PDIM * NPAT];
__device__ unsigned int g_poutb[NPAIRS * DDIM / 2];       // bf16x2, 16.8 MB

__device__ __forceinline__ float my_silu(float z) {
    return z / (1.0f + __expf(-z));
}

__device__ __forceinline__ void mma_tf32(float& c0, float& c1, float& c2, float& c3,
                                         unsigned int a0, unsigned int a1,
                                         unsigned int a2, unsigned int a3,
                                         unsigned int b0, unsigned int b1) {
    asm volatile(
        "mma.sync.aligned.m16n8k8.row.col.f32.tf32.tf32.f32 "
        "{%0,%1,%2,%3}, {%4,%5,%6,%7}, {%8,%9}, {%0,%1,%2,%3};"
        : "+f"(c0), "+f"(c1), "+f"(c2), "+f"(c3)
        : "r"(a0), "r"(a1), "r"(a2), "r"(a3), "r"(b0), "r"(b1));
}

__device__ __forceinline__ void cp_async16(unsigned int dst, const void* src) {
    asm volatile("cp.async.cg.shared.global [%0], [%1], 16;" :: "r"(dst), "l"(src));
}
__device__ __forceinline__ void cp_commit() {
    asm volatile("cp.async.commit_group;");
}
template<int N> __device__ __forceinline__ void cp_wait() {
    asm volatile("cp.async.wait_group %0;" :: "n"(N));
}

// ---------------- kernel 0: transpose hasher_w and keys ----------------
__global__ void prep_kernel(const float* __restrict__ hw,
                            const float* __restrict__ keys)
{
    const int tid = blockIdx.x * 256 + threadIdx.x;
    if (tid < (PDIM * DDIM) / 4) {
        const int p = tid >> 8;
        const float4 v = ((const float4*)hw)[tid];
        const int d = (tid & 255) * 4;
        g_hwT[(d + 0) * PDIM + p] = v.x;
        g_hwT[(d + 1) * PDIM + p] = v.y;
        g_hwT[(d + 2) * PDIM + p] = v.z;
        g_hwT[(d + 3) * PDIM + p] = v.w;
    }
    if (tid < (NPAT * PDIM) / 4) {
        const int n = tid >> 3;
        const int q = tid & 7;
        const float4 v = ((const float4*)keys)[tid];
        g_keysT[(q * 4 + 0) * NPAT + n] = v.x;
        g_keysT[(q * 4 + 1) * NPAT + n] = v.y;
        g_keysT[(q * 4 + 2) * NPAT + n] = v.z;
        g_keysT[(q * 4 + 3) * NPAT + n] = v.w;
    }
}

// ---------------- kernel 1: routing — 8 tokens/block, 256 blocks ----------------
__global__ __launch_bounds__(256)
void routing_kernel(const float* __restrict__ x,
                    const float* __restrict__ scale)
{
    __shared__ float wS[256 * WPAD];
    __shared__ float shh[8][PDIM];

    const int tid  = threadIdx.x;
    const int warp = tid >> 5;
    const int lane = tid & 31;
    const int tok  = blockIdx.x * 8 + warp;

    const int p4 = lane & 7;
    const int dq = lane >> 3;

    float4 acc = make_float4(0.f, 0.f, 0.f, 0.f);
    const float* xr0 = x + (size_t)tok * DDIM;

    for (int slice = 0; slice < 4; slice++) {
        __syncthreads();
        {
            const float4* src = (const float4*)(g_hwT + slice * 256 * PDIM);
            #pragma unroll
            for (int k = 0; k < 8; k++) {
                const int i = tid + k * 256;
                const int r = i >> 3, q = i & 7;
                *(float4*)&wS[r * WPAD + q * 4] = src[i];
            }
        }
        __syncthreads();

        const float* xr = xr0 + slice * 256;
        #pragma unroll 2
        for (int db = 0; db < 256; db += 16) {
            const float4 xv = *(const float4*)(xr + db + dq * 4);
            const int wb = (db + dq * 4) * WPAD + p4 * 4;
            #pragma unroll
            for (int j = 0; j < 4; j++) {
                const float4 w = *(const float4*)&wS[wb + j * WPAD];
                const float s = (j==0)?xv.x:(j==1)?xv.y:(j==2)?xv.z:xv.w;
                acc.x += s*w.x; acc.y += s*w.y; acc.z += s*w.z; acc.w += s*w.w;
            }
        }
    }

    #pragma unroll
    for (int o = 8; o <= 16; o <<= 1) {
        acc.x += __shfl_xor_sync(0xFFFFFFFFu, acc.x, o);
        acc.y += __shfl_xor_sync(0xFFFFFFFFu, acc.y, o);
        acc.z += __shfl_xor_sync(0xFFFFFFFFu, acc.z, o);
        acc.w += __shfl_xor_sync(0xFFFFFFFFu, acc.w, o);
    }
    if (dq == 0) *(float4*)&shh[warp][p4 * 4] = acc;
    __syncthreads();

    {
        const float4* src = (const float4*)g_keysT;
        #pragma unroll
        for (int k = 0; k < 8; k++)
            ((float4*)wS)[tid + k * 256] = src[tid + k * 256];
    }
    __syncthreads();

    float v[8];
    #pragma unroll
    for (int j = 0; j < 8; j++) v[j] = 0.f;
    #pragma unroll 4
    for (int p = 0; p < PDIM; p++) {
        const float hp = shh[warp][p];
        const int kb = p * NPAT + lane;
        #pragma unroll
        for (int j = 0; j < 8; j++)
            v[j] += hp * wS[kb + 32 * j];
    }

    float wv[TOPK]; int widx[TOPK];
    #pragma unroll
    for (int k = 0; k < TOPK; k++) {
        float bv = v[0]; int bj = 0;
        #pragma unroll
        for (int j = 1; j < 8; j++)
            if (v[j] > bv) { bv = v[j]; bj = j; }
        int bidx = lane + 32 * bj;
        #pragma unroll
        for (int o = 16; o; o >>= 1) {
            float ov = __shfl_xor_sync(0xFFFFFFFFu, bv, o);
            int   oi = __shfl_xor_sync(0xFFFFFFFFu, bidx, o);
            if (ov > bv || (ov == bv && oi < bidx)) { bv = ov; bidx = oi; }
        }
        wv[k] = bv; widx[k] = bidx;
        if ((bidx & 31) == lane) v[bidx >> 5] = -1e30f;
    }

    if (lane == 0) {
        float m = wv[0];
        #pragma unroll
        for (int k = 1; k < TOPK; k++) m = fmaxf(m, wv[k]);
        float e[TOPK], s = 0.0f;
        #pragma unroll
        for (int k = 0; k < TOPK; k++) { e[k] = __expf(wv[k] - m); s += e[k]; }
        const float inv = scale[0] / s;
        #pragma unroll
        for (int k = 0; k < TOPK; k++) {
            const int pair = (tok << 2) | k;
            g_eidx[pair] = widx[k];
            g_wt[pair]   = e[k] * inv;
        }
    }
}

// ---------------- kernel 2: scheduler ----------------
__global__ __launch_bounds__(NPAT, 1)
void build_tiles_kernel()
{
    __shared__ int cnt[NPAT];
    __shared__ int scn[NPAT];
    __shared__ int base[NPAT];
    __shared__ int off[NPAT];

    const int t = threadIdx.x;
    cnt[t] = 0; off[t] = 0;
    __syncthreads();

    for (int i = t; i < NPAIRS; i += NPAT)
        atomicAdd(&cnt[g_eidx[i]], 1);
    __syncthreads();

    scn[t] = cnt[t];
    __syncthreads();
    for (int o = 1; o < NPAT; o <<= 1) {
        int add = (t >= o) ? scn[t - o] : 0;
        __syncthreads();
        scn[t] += add;
        __syncthreads();
    }
    base[t] = scn[t] - cnt[t];
    __syncthreads();

    for (int i = t; i < NPAIRS; i += NPAT) {
        const int e = g_eidx[i];
        const int slot = atomicAdd(&off[e], 1);
        g_list[base[e] + slot] = i;
    }

    const int nch = (cnt[t] + CHUNK - 1) / CHUNK;
    scn[t] = nch;
    __syncthreads();
    for (int o = 1; o < NPAT; o <<= 1) {
        int add = (t >= o) ? scn[t - o] : 0;
        __syncthreads();
        scn[t] += add;
        __syncthreads();
    }
    const int cbase = scn[t] - nch;
    for (int i = 0; i < nch; i++) {
        const int start = base[t] + i * CHUNK;
        const int c     = min(CHUNK, cnt[t] - i * CHUNK);
        g_tiles[cbase + i] = (t << 19) | (start << 6) | c;
    }
    if (t == NPAT - 1) g_nchunks = scn[t];
}

// ---------------- kernel 3: fused expert — cp.async pipeline + TF32 mma ----------------
// one block per chunk. dyn smem: buf0[8832] | buf1[8832] | projS[32*36]
__global__ __launch_bounds__(256)
void expert_kernel(const float* __restrict__ x,
                   const float* __restrict__ vd,
                   const float* __restrict__ vu)
{
    extern __shared__ float sm[];
    float* projS = sm + 2 * BUFSZ;
    __shared__ int   spair[CHUNK];
    __shared__ float wtS[CHUNK];

    const int chunkId = blockIdx.x;
    if (chunkId >= g_nchunks) return;

    const int te    = g_tiles[chunkId];
    const int e     = te >> 19;
    const int start = (te >> 6) & 0x1FFF;
    const int cnt   = te & 0x3F;

    const int tid = threadIdx.x;
    if (tid < CHUNK) {
        const int pr = g_list[start + min(tid, cnt - 1)];
        spair[tid] = pr;
        wtS[tid]   = g_wt[pr];
    }
    __syncthreads();

    const int warp = tid >> 5;
    const int lane = tid & 31;
    const int grp  = lane >> 2;
    const int t4   = lane & 3;

    // staging issue helpers (each thread: 8 cp.async for A-stage, 4 for B-stage)
    auto issueA = [&](int s, float* b) {
        const unsigned int wbase = (unsigned int)__cvta_generic_to_shared(b);
        const unsigned int xbase = (unsigned int)__cvta_generic_to_shared(b + 4608);
        const float* wsrc = vd + ((size_t)e * DDIM + s * 128) * PDIM;
        #pragma unroll
        for (int k = 0; k < 4; k++) {
            const int i = tid + k * 256;          // 0..1023
            const int r = i >> 3, q = i & 7;
            cp_async16(wbase + (r * WPAD + q * 4) * 4, wsrc + r * PDIM + q * 4);
        }
        #pragma unroll
        for (int k = 0; k < 4; k++) {
            const int i = tid + k * 256;
            const int r = i >> 5, c = i & 31;
            const float* xsrc = x + (size_t)(spair[r] >> 2) * DDIM + s * 128 + c * 4;
            cp_async16(xbase + (r * SSTRIDE + c * 4) * 4, xsrc);
        }
    };
    auto issueB = [&](int s, float* b) {
        const unsigned int vbase = (unsigned int)__cvta_generic_to_shared(b);
        const float* vsrc = vu + (size_t)e * PDIM * DDIM + s * 128;
        #pragma unroll
        for (int k = 0; k < 4; k++) {
            const int i = tid + k * 256;
            const int p = i >> 5, c = i & 31;
            cp_async16(vbase + (p * SSTRIDE + c * 4) * 4, vsrc + p * DDIM + c * 4);
        }
    };

    // ===== phase A: proj[32 tok][32 p] accumulated in registers =====
    const int mt = warp & 1;        // m-tile (tokens 16*mt..)
    const int nt = warp >> 1;       // n-tile (p cols 8*nt..)
    float c0 = 0.f, c1 = 0.f, c2 = 0.f, c3 = 0.f;

    issueA(0, sm); cp_commit();
    for (int s = 0; s < 8; s++) {
        float* nb = sm + (((s + 1) & 1) ? BUFSZ : 0);
        if (s < 7) { issueA(s + 1, nb); cp_commit(); }
        else       { issueB(0, nb);     cp_commit(); }   // prefetch first Vu slice into buf0
        cp_wait<1>();
        __syncthreads();

        const float* b  = sm + ((s & 1) ? BUFSZ : 0);
        const float* xb = b + 4608;
        const int arow0 = (mt * 16 + grp) * SSTRIDE + t4;
        #pragma unroll
        for (int kk = 0; kk < 16; kk++) {
            const int kb = kk * 8;
            const unsigned int a0 = __float_as_uint(xb[arow0 + kb]);
            const unsigned int a1 = __float_as_uint(xb[arow0 + 8 * SSTRIDE + kb]);
            const unsigned int a2 = __float_as_uint(xb[arow0 + kb + 4]);
            const unsigned int a3 = __float_as_uint(xb[arow0 + 8 * SSTRIDE + kb + 4]);
            const unsigned int b0 = __float_as_uint(b[(kb + t4) * WPAD + nt * 8 + grp]);
            const unsigned int b1 = __float_as_uint(b[(kb + t4 + 4) * WPAD + nt * 8 + grp]);
            mma_tf32(c0, c1, c2, c3, a0, a1, a2, a3, b0, b1);
        }
        __syncthreads();
    }

    // silu + gate weight, write projS [32][36]
    {
        const int row0 = mt * 16 + grp;
        const int col  = nt * 8 + t4 * 2;
        const float w0 = wtS[row0], w1 = wtS[row0 + 8];
        projS[row0 * WPAD + col]           = w0 * my_silu(c0);
        projS[row0 * WPAD + col + 1]       = w0 * my_silu(c1);
        projS[(row0 + 8) * WPAD + col]     = w1 * my_silu(c2);
        projS[(row0 + 8) * WPAD + col + 1] = w1 * my_silu(c3);
    }
    __syncthreads();

    // ===== phase B: pout[32 tok][1024 d] streamed per 128-d slice =====
    for (int s = 0; s < 8; s++) {
        if (s < 7) { issueB(s + 1, sm + (((s + 1) & 1) ? BUFSZ : 0)); cp_commit(); }
        if (s < 7) cp_wait<1>(); else cp_wait<0>();
        __syncthreads();

        const float* vb = sm + ((s & 1) ? BUFSZ : 0);

        float d[2][2][4];
        #pragma unroll
        for (int m2 = 0; m2 < 2; m2++)
            #pragma unroll
            for (int n2 = 0; n2 < 2; n2++)
                #pragma unroll
                for (int j = 0; j < 4; j++) d[m2][n2][j] = 0.f;

        #pragma unroll
        for (int kk = 0; kk < 4; kk++) {
            const int kb = kk * 8;
            #pragma unroll
            for (int m2 = 0; m2 < 2; m2++) {
                const int r0 = (m2 * 16 + grp) * WPAD + kb + t4;
                const unsigned int a0 = __float_as_uint(projS[r0]);
                const unsigned int a1 = __float_as_uint(projS[r0 + 8 * WPAD]);
                const unsigned int a2 = __float_as_uint(projS[r0 + 4]);
                const unsigned int a3 = __float_as_uint(projS[r0 + 8 * WPAD + 4]);
                #pragma unroll
                for (int n2 = 0; n2 < 2; n2++) {
                    const int n0 = warp * 16 + n2 * 8;
                    const unsigned int b0 = __float_as_uint(vb[(kb + t4) * SSTRIDE + n0 + grp]);
                    const unsigned int b1 = __float_as_uint(vb[(kb + t4 + 4) * SSTRIDE + n0 + grp]);
                    mma_tf32(d[m2][n2][0], d[m2][n2][1], d[m2][n2][2], d[m2][n2][3],
                             a0, a1, a2, a3, b0, b1);
                }
            }
        }

        // write bf16 pout for this slice
        #pragma unroll
        for (int m2 = 0; m2 < 2; m2++) {
            const int tok0 = m2 * 16 + grp;
            const int tok1 = tok0 + 8;
            #pragma unroll
            for (int n2 = 0; n2 < 2; n2++) {
                const int col = s * 128 + warp * 16 + n2 * 8 + t4 * 2;
                if (tok0 < cnt) {
                    __nv_bfloat162 v = __floats2bfloat162_rn(d[m2][n2][0], d[m2][n2][1]);
                    g_poutb[(spair[tok0] * DDIM + col) >> 1] = *(unsigned int*)&v;
                }
                if (tok1 < cnt) {
                    __nv_bfloat162 v = __floats2bfloat162_rn(d[m2][n2][2], d[m2][n2][3]);
                    g_poutb[(spair[tok1] * DDIM + col) >> 1] = *(unsigned int*)&v;
                }
            }
        }
        __syncthreads();
    }
}

// ---------------- kernel 4: combine ----------------
__global__ __launch_bounds__(256)
void combine_kernel(const float* __restrict__ x, float* __restrict__ out)
{
    const int tok = blockIdx.x;
    const int t   = threadIdx.x;
    float4 o = ((const float4*)(x + (size_t)tok * DDIM))[t];
    #pragma unroll
    for (int k = 0; k < TOPK; k++) {
        const uint2 u = *(const uint2*)&g_poutb[((tok << 2) | k) * (DDIM / 2) + t * 2];
        const __nv_bfloat162 lo = *(const __nv_bfloat162*)&u.x;
        const __nv_bfloat162 hi = *(const __nv_bfloat162*)&u.y;
        const float2 flo = __bfloat1622float2(lo);
        const float2 fhi = __bfloat1622float2(hi);
        o.x += flo.x; o.y += flo.y; o.z += fhi.x; o.w += fhi.y;
    }
    ((float4*)(out + (size_t)tok * DDIM))[t] = o;
}

// ---------------- launch ----------------
extern "C" void kernel_launch(void* const* d_in, const int* in_sizes, int n_in,
                              void* d_out, int out_size) {
    const float* x     = (const float*)d_in[0];
    const float* hw    = (const float*)d_in[1];
    const float* keys  = (const float*)d_in[2];
    const float* vd    = (const float*)d_in[3];
    const float* vu    = (const float*)d_in[4];
    const float* scale = (const float*)d_in[5];
    float* out = (float*)d_out;

    const int smemE = (2 * BUFSZ + CHUNK * WPAD) * (int)sizeof(float);  // 75264 B
    cudaFuncSetAttribute(expert_kernel,
                         cudaFuncAttributeMaxDynamicSharedMemorySize, smemE);

    prep_kernel<<<32, 256>>>(hw, keys);
    routing_kernel<<<TOKENS / 8, 256>>>(x, scale);
    build_tiles_kernel<<<1, NPAT>>>();
    expert_kernel<<<MAXCHUNKS, 256, smemE>>>(x, vd, vu);
    combine_kernel<<<TOKENS, 256>>>(x, out);
}